// round 13
// baseline (speedup 1.0000x reference)
#include <cuda_runtime.h>
#include <cstdint>

#define SS     2048
#define BBATCH 4
#define DDIM   1024
#define HH     16
#define DK     64
#define MM     (SS * BBATCH)
#define LOG2E  1.44269504f
#define QSCALE 0.125f

// ---------------- device scratch ----------------
__device__ uint32_t g_Qp[(size_t)BBATCH * HH * SS * DK];  // [B,H,S,DK] tf32 bits (scaled)
__device__ uint32_t g_Kp[(size_t)BBATCH * HH * SS * DK];
__device__ uint32_t g_Vp[(size_t)BBATCH * HH * SS * DK];
__device__ float    g_Xr[(size_t)MM * DDIM];              // attn out, fp32

// ---------------- helpers ----------------
__device__ __forceinline__ uint32_t f2tf32(float f) {
    uint32_t u;
    asm("cvt.rna.tf32.f32 %0, %1;" : "=r"(u) : "f"(f));
    return u;
}
__device__ __forceinline__ float ex2(float x) {
    float y; asm("ex2.approx.f32 %0, %1;" : "=f"(y) : "f"(x)); return y;
}
__device__ __forceinline__ void mma_tf32(
    float& d0, float& d1, float& d2, float& d3,
    uint32_t a0, uint32_t a1, uint32_t a2, uint32_t a3,
    uint32_t b0, uint32_t b1)
{
    asm volatile(
        "mma.sync.aligned.m16n8k8.row.col.f32.tf32.tf32.f32 "
        "{%0,%1,%2,%3}, {%4,%5,%6,%7}, {%8,%9}, {%0,%1,%2,%3};"
        : "+f"(d0), "+f"(d1), "+f"(d2), "+f"(d3)
        : "r"(a0), "r"(a1), "r"(a2), "r"(a3), "r"(b0), "r"(b1));
}
__device__ __forceinline__ void ldsm_x4(uint32_t& r0, uint32_t& r1,
                                        uint32_t& r2, uint32_t& r3, uint32_t saddr)
{
    asm volatile("ldmatrix.sync.aligned.m8n8.x4.shared.b16 {%0,%1,%2,%3}, [%4];"
                 : "=r"(r0), "=r"(r1), "=r"(r2), "=r"(r3) : "r"(saddr));
}

// ---------------------------------------------------------------------------
// tf32 GEMM (unchanged from R11): C = A @ W^T + bias, cvt folded into loader.
// Block 128x128, 4 warps, warp tile 64x64, BK=16, double-buffered smem,
// ldmatrix.x4 fragments.
// ---------------------------------------------------------------------------
#define GPAD 20
#define GSTG (128 * GPAD)

__device__ __forceinline__ void gemm_body(
    const float* __restrict__ A, const float* __restrict__ W,
    const float* __restrict__ bias, float* __restrict__ out_ext, int sel)
{
    __shared__ __align__(16) uint32_t As[2 * GSTG];
    __shared__ __align__(16) uint32_t Ws[2 * GSTG];
    const uint32_t abase = (uint32_t)__cvta_generic_to_shared(As);
    const uint32_t wbase = (uint32_t)__cvta_generic_to_shared(Ws);

    const int tid  = threadIdx.x;       // 0..127
    const int lane = tid & 31;
    const int warp = tid >> 5;          // 0..3
    const int wm64 = (warp & 1) * 64;
    const int wn64 = (warp >> 1) * 64;
    const int g    = lane >> 2;
    const int t    = lane & 3;
    const int m0 = blockIdx.y * 128;
    const int n0 = blockIdx.x * 128;

    const uint32_t aoff = (((wm64 + ((lane >> 3) & 1) * 8 + (lane & 7)) * GPAD
                           + ((lane >> 4) << 2)) << 2);
    const uint32_t boff = (((wn64 + ((lane >> 4) << 3) + (lane & 7)) * GPAD
                           + (((lane >> 3) & 1) << 2)) << 2);

    int lrow[4], lq[4];
#pragma unroll
    for (int i = 0; i < 4; i++) {
        const int c = tid + i * 128;
        lrow[i] = c >> 2;
        lq[i]   = (c & 3) * 4;
    }

    float acc[4][8][4];
#pragma unroll
    for (int mt = 0; mt < 4; mt++)
#pragma unroll
        for (int nt = 0; nt < 8; nt++)
#pragma unroll
            for (int e = 0; e < 4; e++) acc[mt][nt][e] = 0.f;

    float4 ast[4], wst[4];
#pragma unroll
    for (int i = 0; i < 4; i++) {
        ast[i] = *(const float4*)(A + (size_t)(m0 + lrow[i]) * DDIM + lq[i]);
        wst[i] = *(const float4*)(W + (size_t)(n0 + lrow[i]) * DDIM + lq[i]);
    }

    const int KT = DDIM / 16;  // 64
    for (int kt = 0; kt < KT; kt++) {
        const int s = kt & 1;
#pragma unroll
        for (int i = 0; i < 4; i++) {
            uint4 ac = make_uint4(f2tf32(ast[i].x), f2tf32(ast[i].y),
                                  f2tf32(ast[i].z), f2tf32(ast[i].w));
            uint4 wc = make_uint4(f2tf32(wst[i].x), f2tf32(wst[i].y),
                                  f2tf32(wst[i].z), f2tf32(wst[i].w));
            *(uint4*)&As[s * GSTG + lrow[i] * GPAD + lq[i]] = ac;
            *(uint4*)&Ws[s * GSTG + lrow[i] * GPAD + lq[i]] = wc;
        }
        __syncthreads();
        if (kt + 1 < KT) {
            const int k0 = (kt + 1) * 16;
#pragma unroll
            for (int i = 0; i < 4; i++) {
                ast[i] = *(const float4*)(A + (size_t)(m0 + lrow[i]) * DDIM + k0 + lq[i]);
                wst[i] = *(const float4*)(W + (size_t)(n0 + lrow[i]) * DDIM + k0 + lq[i]);
            }
        }

        const uint32_t asb = abase + s * (GSTG * 4);
        const uint32_t wsb = wbase + s * (GSTG * 4);
#pragma unroll
        for (int kk = 0; kk < 16; kk += 8) {
            uint32_t a[4][4];
#pragma unroll
            for (int mt = 0; mt < 4; mt++)
                ldsm_x4(a[mt][0], a[mt][1], a[mt][2], a[mt][3],
                        asb + aoff + (uint32_t)(mt * 16 * GPAD + kk) * 4);
            uint32_t b[8][2];
#pragma unroll
            for (int p = 0; p < 4; p++)
                ldsm_x4(b[2 * p][0], b[2 * p][1], b[2 * p + 1][0], b[2 * p + 1][1],
                        wsb + boff + (uint32_t)(p * 16 * GPAD + kk) * 4);
#pragma unroll
            for (int mt = 0; mt < 4; mt++)
#pragma unroll
                for (int nt = 0; nt < 8; nt++)
                    mma_tf32(acc[mt][nt][0], acc[mt][nt][1], acc[mt][nt][2], acc[mt][nt][3],
                             a[mt][0], a[mt][1], a[mt][2], a[mt][3],
                             b[nt][0], b[nt][1]);
        }
        __syncthreads();
    }

    uint32_t* scat = (sel == 0) ? g_Qp : (sel == 1) ? g_Kp : g_Vp;
#pragma unroll
    for (int mt = 0; mt < 4; mt++) {
#pragma unroll
        for (int nt = 0; nt < 8; nt++) {
            const int cg = n0 + wn64 + nt * 8 + 2 * t;
            const float b0 = bias[cg], b1 = bias[cg + 1];
#pragma unroll
            for (int half = 0; half < 2; half++) {
                const int rg_ = m0 + wm64 + mt * 16 + g + 8 * half;
                float v0 = acc[mt][nt][half * 2 + 0] + b0;
                float v1 = acc[mt][nt][half * 2 + 1] + b1;
                if (sel < 3) {
                    if (sel == 0) { v0 *= QSCALE; v1 *= QSCALE; }
                    const int s_ = rg_ >> 2, b_ = rg_ & 3;
                    const int h_ = cg >> 6,  dk = cg & 63;
                    uint2 o = make_uint2(f2tf32(v0), f2tf32(v1));
                    *(uint2*)&scat[(((size_t)(b_ * HH + h_)) * SS + s_) * DK + dk] = o;
                } else {
                    *(float2*)&out_ext[(size_t)rg_ * DDIM + cg] = make_float2(v0, v1);
                }
            }
        }
    }
}

__global__ void __launch_bounds__(128, 2) gemm_qkv2(
    const float* __restrict__ q, const float* __restrict__ k,
    const float* __restrict__ v,
    const float* __restrict__ wq, const float* __restrict__ wk,
    const float* __restrict__ wv,
    const float* __restrict__ bq, const float* __restrict__ bk,
    const float* __restrict__ bv)
{
    const int sel = blockIdx.z;
    const float* A = (sel == 0) ? q : (sel == 1) ? k : v;
    const float* W = (sel == 0) ? wq : (sel == 1) ? wk : wv;
    const float* bias = (sel == 0) ? bq : (sel == 1) ? bk : bv;
    gemm_body(A, W, bias, nullptr, sel);
}

__global__ void __launch_bounds__(128, 2) gemm_out(
    const float* __restrict__ wo, const float* __restrict__ bo,
    float* __restrict__ out)
{
    gemm_body(g_Xr, wo, bo, out, 3);
}

// ---------------------------------------------------------------------------
// Tensor-core causal flash attention, 2 CTAs/SM.
// CTA: 128 q-rows, 128 threads = 4 warps x 32-row warp tiles.
// K/V: 64-key tiles, single smem buffer + register-staged prefetch.
// smem = Q[128][68] + P[128][68] + K[64][68] + V[64][68] = 104448 B.
// ---------------------------------------------------------------------------
#define AR    68
#define AT_SMEM ((2 * 128 * AR + 2 * 64 * AR) * 4)   // 104448 B

__global__ void __launch_bounds__(128, 2) attn_tc()
{
    extern __shared__ uint32_t dsm_a[];
    uint32_t* Qsm = dsm_a;                 // [128][AR]
    uint32_t* Psm = Qsm + 128 * AR;        // [128][AR]
    uint32_t* Ksm = Psm + 128 * AR;        // [64][AR]
    uint32_t* Vsm = Ksm + 64 * AR;         // [64][AR]
    const uint32_t qsm_b = (uint32_t)__cvta_generic_to_shared(Qsm);
    const uint32_t psm_b = (uint32_t)__cvta_generic_to_shared(Psm);
    const uint32_t ksm_b = (uint32_t)__cvta_generic_to_shared(Ksm);

    const int bh   = blockIdx.x;
    const int qb   = (gridDim.y - 1) - blockIdx.y;   // heavy blocks first
    const int q0   = qb * 128;
    const int tid  = threadIdx.x;          // 0..127
    const int lane = tid & 31;
    const int warp = tid >> 5;             // 0..3
    const int g    = lane >> 2;
    const int t    = lane & 3;
    const int lr0  = warp * 32;

    const uint32_t a_ln = ((((lane >> 3) & 1) * 8 + (lane & 7)) * AR
                           + ((lane >> 4) << 2)) << 2;
    const uint32_t b_ln = (((((lane >> 4) << 3) + (lane & 7)) * AR)
                           + (((lane >> 3) & 1) << 2)) << 2;

    const uint32_t* Qg = g_Qp + (size_t)bh * SS * DK + (size_t)q0 * DK;
    const uint32_t* Kg = g_Kp + (size_t)bh * SS * DK;
    const uint32_t* Vg = g_Vp + (size_t)bh * SS * DK;

    const int ntiles = 2 * qb + 2;

    // K/V loader coords: 64 rows x 16 uint4 = 1024 chunks; 8 per thread
    int lrow[8], lq[8];
#pragma unroll
    for (int i = 0; i < 8; i++) {
        const int c = tid + i * 128;
        lrow[i] = c >> 4;
        lq[i]   = (c & 15) * 4;
    }

    // Stage Q: 128 rows x 16 uint4 = 2048 chunks; 16 per thread (FIXED)
#pragma unroll
    for (int i = 0; i < 16; i++) {
        const int idx = tid + i * 128;
        const int row = idx >> 4;
        const int cq  = (idx & 15) * 4;
        *(uint4*)&Qsm[row * AR + cq] = *(const uint4*)(Qg + (size_t)row * DK + cq);
    }

    uint4 kst[8], vst[8];
#pragma unroll
    for (int i = 0; i < 8; i++) {
        kst[i] = *(const uint4*)(Kg + (size_t)lrow[i] * DK + lq[i]);
        vst[i] = *(const uint4*)(Vg + (size_t)lrow[i] * DK + lq[i]);
    }

    float m_[4], l_[4];
#pragma unroll
    for (int i = 0; i < 4; i++) { m_[i] = -1e30f; l_[i] = 0.f; }
    float oacc[2][8][4];
#pragma unroll
    for (int mt = 0; mt < 2; mt++)
#pragma unroll
        for (int nt = 0; nt < 8; nt++)
#pragma unroll
            for (int e = 0; e < 4; e++) oacc[mt][nt][e] = 0.f;

    for (int kt = 0; kt < ntiles; kt++) {
        const int kbase = kt * 64;

        // store staged K/V tile (previous reads finished at loop-end barrier)
#pragma unroll
        for (int i = 0; i < 8; i++) {
            *(uint4*)&Ksm[lrow[i] * AR + lq[i]] = kst[i];
            *(uint4*)&Vsm[lrow[i] * AR + lq[i]] = vst[i];
        }
        __syncthreads();

        // prefetch next tile into registers (overlaps compute)
        if (kt + 1 < ntiles) {
            const size_t base = (size_t)(kt + 1) * 64 * DK;
#pragma unroll
            for (int i = 0; i < 8; i++) {
                kst[i] = *(const uint4*)(Kg + base + (size_t)lrow[i] * DK + lq[i]);
                vst[i] = *(const uint4*)(Vg + base + (size_t)lrow[i] * DK + lq[i]);
            }
        }

        if (kbase <= q0 + lr0 + 31) {
            // ---- S = Q K^T (32 x 64) ----
            float sacc[2][8][4];
#pragma unroll
            for (int mt = 0; mt < 2; mt++)
#pragma unroll
                for (int nt = 0; nt < 8; nt++)
#pragma unroll
                    for (int e = 0; e < 4; e++) sacc[mt][nt][e] = 0.f;

#pragma unroll
            for (int kk = 0; kk < 8; kk++) {
                uint32_t aq[2][4];
#pragma unroll
                for (int mt = 0; mt < 2; mt++)
                    ldsm_x4(aq[mt][0], aq[mt][1], aq[mt][2], aq[mt][3],
                            qsm_b + a_ln + (uint32_t)(((lr0 + mt * 16) * AR + kk * 8) * 4));
                uint32_t b[8][2];
#pragma unroll
                for (int p = 0; p < 4; p++)
                    ldsm_x4(b[2 * p][0], b[2 * p][1], b[2 * p + 1][0], b[2 * p + 1][1],
                            ksm_b + b_ln + (uint32_t)((p * 16 * AR + kk * 8) * 4));
#pragma unroll
                for (int nt = 0; nt < 8; nt++)
#pragma unroll
                    for (int mt = 0; mt < 2; mt++)
                        mma_tf32(sacc[mt][nt][0], sacc[mt][nt][1], sacc[mt][nt][2], sacc[mt][nt][3],
                                 aq[mt][0], aq[mt][1], aq[mt][2], aq[mt][3],
                                 b[nt][0], b[nt][1]);
            }

            // ---- causal mask (diagonal band only) ----
            if (kbase + 63 > q0 + lr0) {
#pragma unroll
                for (int mt = 0; mt < 2; mt++) {
                    const int rt_ = q0 + lr0 + mt * 16 + g;
                    const int rb_ = rt_ + 8;
#pragma unroll
                    for (int nt = 0; nt < 8; nt++) {
                        const int c0 = kbase + nt * 8 + 2 * t;
                        if (c0 > rt_)     sacc[mt][nt][0] = -1e30f;
                        if (c0 + 1 > rt_) sacc[mt][nt][1] = -1e30f;
                        if (c0 > rb_)     sacc[mt][nt][2] = -1e30f;
                        if (c0 + 1 > rb_) sacc[mt][nt][3] = -1e30f;
                    }
                }
            }

            // ---- online softmax ----
#pragma unroll
            for (int mt = 0; mt < 2; mt++) {
                float mxt = -1e30f, mxb = -1e30f;
#pragma unroll
                for (int nt = 0; nt < 8; nt++) {
                    mxt = fmaxf(mxt, fmaxf(sacc[mt][nt][0], sacc[mt][nt][1]));
                    mxb = fmaxf(mxb, fmaxf(sacc[mt][nt][2], sacc[mt][nt][3]));
                }
                mxt = fmaxf(mxt, __shfl_xor_sync(0xffffffffu, mxt, 1));
                mxt = fmaxf(mxt, __shfl_xor_sync(0xffffffffu, mxt, 2));
                mxb = fmaxf(mxb, __shfl_xor_sync(0xffffffffu, mxb, 1));
                mxb = fmaxf(mxb, __shfl_xor_sync(0xffffffffu, mxb, 2));

                const int rc0 = mt * 2, rc1 = mt * 2 + 1;
                const float mnt = fmaxf(m_[rc0], mxt);
                const float mnb = fmaxf(m_[rc1], mxb);
                const float ct = ex2((m_[rc0] - mnt) * LOG2E);
                const float cb = ex2((m_[rc1] - mnb) * LOG2E);
                m_[rc0] = mnt; m_[rc1] = mnb;

                float st_ = 0.f, sb_ = 0.f;
                uint32_t* pr0 = Psm + (lr0 + mt * 16 + g) * AR;
                uint32_t* pr1 = pr0 + 8 * AR;
#pragma unroll
                for (int nt = 0; nt < 8; nt++) {
                    const float p0 = ex2((sacc[mt][nt][0] - mnt) * LOG2E);
                    const float p1 = ex2((sacc[mt][nt][1] - mnt) * LOG2E);
                    const float p2 = ex2((sacc[mt][nt][2] - mnb) * LOG2E);
                    const float p3 = ex2((sacc[mt][nt][3] - mnb) * LOG2E);
                    st_ += p0 + p1; sb_ += p2 + p3;
                    pr0[nt * 8 + 2 * t]     = f2tf32(p0);
                    pr0[nt * 8 + 2 * t + 1] = f2tf32(p1);
                    pr1[nt * 8 + 2 * t]     = f2tf32(p2);
                    pr1[nt * 8 + 2 * t + 1] = f2tf32(p3);
                }
                st_ += __shfl_xor_sync(0xffffffffu, st_, 1);
                st_ += __shfl_xor_sync(0xffffffffu, st_, 2);
                sb_ += __shfl_xor_sync(0xffffffffu, sb_, 1);
                sb_ += __shfl_xor_sync(0xffffffffu, sb_, 2);
                l_[rc0] = l_[rc0] * ct + st_;
                l_[rc1] = l_[rc1] * cb + sb_;
#pragma unroll
                for (int nt = 0; nt < 8; nt++) {
                    oacc[mt][nt][0] *= ct; oacc[mt][nt][1] *= ct;
                    oacc[mt][nt][2] *= cb; oacc[mt][nt][3] *= cb;
                }
            }
            __syncwarp();

            // ---- O += P V (32 x 64 x 64) ----
#pragma unroll
            for (int kk = 0; kk < 8; kk++) {
                uint32_t ap[2][4];
#pragma unroll
                for (int mt = 0; mt < 2; mt++)
                    ldsm_x4(ap[mt][0], ap[mt][1], ap[mt][2], ap[mt][3],
                            psm_b + a_ln + (uint32_t)(((lr0 + mt * 16) * AR + kk * 8) * 4));
                const uint32_t* vp0 = Vsm + (kk * 8 + t) * AR;
                const uint32_t* vp1 = Vsm + (kk * 8 + t + 4) * AR;
#pragma unroll
                for (int nt = 0; nt < 8; nt++) {
                    const uint32_t b0 = vp0[nt * 8 + g];
                    const uint32_t b1 = vp1[nt * 8 + g];
#pragma unroll
                    for (int mt = 0; mt < 2; mt++)
                        mma_tf32(oacc[mt][nt][0], oacc[mt][nt][1], oacc[mt][nt][2], oacc[mt][nt][3],
                                 ap[mt][0], ap[mt][1], ap[mt][2], ap[mt][3], b0, b1);
                }
            }
        }
        __syncthreads();   // K/V reads done before next store
    }

    // ---- epilogue ----
    const int b_ = bh >> 4;
    const int h_ = bh & 15;
#pragma unroll
    for (int mt = 0; mt < 2; mt++) {
#pragma unroll
        for (int half = 0; half < 2; half++) {
            const int rc = mt * 2 + half;
            const float inv = 1.0f / l_[rc];
            const int row = q0 + lr0 + mt * 16 + g + 8 * half;
            float* dst = g_Xr + ((size_t)row * BBATCH + b_) * DDIM + h_ * DK;
#pragma unroll
            for (int nt = 0; nt < 8; nt++) {
                const int c = nt * 8 + 2 * t;
                *(float2*)(dst + c) = make_float2(oacc[mt][nt][half * 2 + 0] * inv,
                                                  oacc[mt][nt][half * 2 + 1] * inv);
            }
        }
    }
}

// ---------------------------------------------------------------------------
// Launch: gemm_qkv2(0), attn(1), gemm_out(2)
// ---------------------------------------------------------------------------
extern "C" void kernel_launch(void* const* d_in, const int* in_sizes, int n_in,
                              void* d_out, int out_size)
{
    (void)in_sizes; (void)n_in; (void)out_size;
    const float* query = (const float*)d_in[0];
    const float* key   = (const float*)d_in[1];
    const float* value = (const float*)d_in[2];
    const float* Wq = (const float*)d_in[4];
    const float* bq = (const float*)d_in[5];
    const float* Wk = (const float*)d_in[6];
    const float* bk = (const float*)d_in[7];
    const float* Wv = (const float*)d_in[8];
    const float* bv = (const float*)d_in[9];
    const float* Wo = (const float*)d_in[10];
    const float* bo = (const float*)d_in[11];
    float* out = (float*)d_out;

    cudaFuncSetAttribute(attn_tc, cudaFuncAttributeMaxDynamicSharedMemorySize, AT_SMEM);

    gemm_qkv2<<<dim3(DDIM / 128, MM / 128, 3), 128>>>(
        query, key, value, Wq, Wk, Wv, bq, bk, bv);

    attn_tc<<<dim3(BBATCH * HH, SS / 128), 128, AT_SMEM>>>();

    gemm_out<<<dim3(DDIM / 128, MM / 128), 128>>>(Wo, bo, out);
}

// round 15
// speedup vs baseline: 1.0240x; 1.0240x over previous
#include <cuda_runtime.h>
#include <cstdint>

#define SS     2048
#define BBATCH 4
#define DDIM   1024
#define HH     16
#define DK     64
#define MM     (SS * BBATCH)
#define LOG2E  1.44269504f
#define QSCALE 0.125f

// ---------------- device scratch ----------------
__device__ uint32_t g_Qp[(size_t)BBATCH * HH * SS * DK];  // [B,H,S,DK] tf32 bits (scaled)
__device__ uint32_t g_Kp[(size_t)BBATCH * HH * SS * DK];
__device__ uint32_t g_Vp[(size_t)BBATCH * HH * SS * DK];
__device__ float    g_Xr[(size_t)MM * DDIM];              // attn out, fp32

// ---------------- helpers ----------------
__device__ __forceinline__ uint32_t f2tf32(float f) {
    uint32_t u;
    asm("cvt.rna.tf32.f32 %0, %1;" : "=r"(u) : "f"(f));
    return u;
}
__device__ __forceinline__ float ex2(float x) {
    float y; asm("ex2.approx.f32 %0, %1;" : "=f"(y) : "f"(x)); return y;
}
__device__ __forceinline__ void mma_tf32(
    float& d0, float& d1, float& d2, float& d3,
    uint32_t a0, uint32_t a1, uint32_t a2, uint32_t a3,
    uint32_t b0, uint32_t b1)
{
    asm volatile(
        "mma.sync.aligned.m16n8k8.row.col.f32.tf32.tf32.f32 "
        "{%0,%1,%2,%3}, {%4,%5,%6,%7}, {%8,%9}, {%0,%1,%2,%3};"
        : "+f"(d0), "+f"(d1), "+f"(d2), "+f"(d3)
        : "r"(a0), "r"(a1), "r"(a2), "r"(a3), "r"(b0), "r"(b1));
}
__device__ __forceinline__ void ldsm_x4(uint32_t& r0, uint32_t& r1,
                                        uint32_t& r2, uint32_t& r3, uint32_t saddr)
{
    asm volatile("ldmatrix.sync.aligned.m8n8.x4.shared.b16 {%0,%1,%2,%3}, [%4];"
                 : "=r"(r0), "=r"(r1), "=r"(r2), "=r"(r3) : "r"(saddr));
}

// ---------------------------------------------------------------------------
// tf32 GEMM: C = A @ W^T + bias, cvt folded into loader.
// Block 128x128, 4 warps, warp tile 64x64, BK=16, double-buffered smem,
// ldmatrix.x4 fragments. ONE barrier per k-iteration (double-buffer-safe:
// reads(kt,slot s) < barrier(kt+1) < store(kt+2,slot s) in program order).
// ---------------------------------------------------------------------------
#define GPAD 20
#define GSTG (128 * GPAD)

__device__ __forceinline__ void gemm_body(
    const float* __restrict__ A, const float* __restrict__ W,
    const float* __restrict__ bias, float* __restrict__ out_ext, int sel)
{
    __shared__ __align__(16) uint32_t As[2 * GSTG];
    __shared__ __align__(16) uint32_t Ws[2 * GSTG];
    const uint32_t abase = (uint32_t)__cvta_generic_to_shared(As);
    const uint32_t wbase = (uint32_t)__cvta_generic_to_shared(Ws);

    const int tid  = threadIdx.x;       // 0..127
    const int lane = tid & 31;
    const int warp = tid >> 5;          // 0..3
    const int wm64 = (warp & 1) * 64;
    const int wn64 = (warp >> 1) * 64;
    const int g    = lane >> 2;
    const int t    = lane & 3;
    const int m0 = blockIdx.y * 128;
    const int n0 = blockIdx.x * 128;

    const uint32_t aoff = (((wm64 + ((lane >> 3) & 1) * 8 + (lane & 7)) * GPAD
                           + ((lane >> 4) << 2)) << 2);
    const uint32_t boff = (((wn64 + ((lane >> 4) << 3) + (lane & 7)) * GPAD
                           + (((lane >> 3) & 1) << 2)) << 2);

    int lrow[4], lq[4];
#pragma unroll
    for (int i = 0; i < 4; i++) {
        const int c = tid + i * 128;
        lrow[i] = c >> 2;
        lq[i]   = (c & 3) * 4;
    }

    float acc[4][8][4];
#pragma unroll
    for (int mt = 0; mt < 4; mt++)
#pragma unroll
        for (int nt = 0; nt < 8; nt++)
#pragma unroll
            for (int e = 0; e < 4; e++) acc[mt][nt][e] = 0.f;

    float4 ast[4], wst[4];
#pragma unroll
    for (int i = 0; i < 4; i++) {
        ast[i] = *(const float4*)(A + (size_t)(m0 + lrow[i]) * DDIM + lq[i]);
        wst[i] = *(const float4*)(W + (size_t)(n0 + lrow[i]) * DDIM + lq[i]);
    }

    const int KT = DDIM / 16;  // 64
    for (int kt = 0; kt < KT; kt++) {
        const int s = kt & 1;
#pragma unroll
        for (int i = 0; i < 4; i++) {
            uint4 ac = make_uint4(f2tf32(ast[i].x), f2tf32(ast[i].y),
                                  f2tf32(ast[i].z), f2tf32(ast[i].w));
            uint4 wc = make_uint4(f2tf32(wst[i].x), f2tf32(wst[i].y),
                                  f2tf32(wst[i].z), f2tf32(wst[i].w));
            *(uint4*)&As[s * GSTG + lrow[i] * GPAD + lq[i]] = ac;
            *(uint4*)&Ws[s * GSTG + lrow[i] * GPAD + lq[i]] = wc;
        }
        __syncthreads();
        if (kt + 1 < KT) {
            const int k0 = (kt + 1) * 16;
#pragma unroll
            for (int i = 0; i < 4; i++) {
                ast[i] = *(const float4*)(A + (size_t)(m0 + lrow[i]) * DDIM + k0 + lq[i]);
                wst[i] = *(const float4*)(W + (size_t)(n0 + lrow[i]) * DDIM + k0 + lq[i]);
            }
        }

        const uint32_t asb = abase + s * (GSTG * 4);
        const uint32_t wsb = wbase + s * (GSTG * 4);
#pragma unroll
        for (int kk = 0; kk < 16; kk += 8) {
            uint32_t a[4][4];
#pragma unroll
            for (int mt = 0; mt < 4; mt++)
                ldsm_x4(a[mt][0], a[mt][1], a[mt][2], a[mt][3],
                        asb + aoff + (uint32_t)(mt * 16 * GPAD + kk) * 4);
            uint32_t b[8][2];
#pragma unroll
            for (int p = 0; p < 4; p++)
                ldsm_x4(b[2 * p][0], b[2 * p][1], b[2 * p + 1][0], b[2 * p + 1][1],
                        wsb + boff + (uint32_t)(p * 16 * GPAD + kk) * 4);
#pragma unroll
            for (int mt = 0; mt < 4; mt++)
#pragma unroll
                for (int nt = 0; nt < 8; nt++)
                    mma_tf32(acc[mt][nt][0], acc[mt][nt][1], acc[mt][nt][2], acc[mt][nt][3],
                             a[mt][0], a[mt][1], a[mt][2], a[mt][3],
                             b[nt][0], b[nt][1]);
        }
    }

    uint32_t* scat = (sel == 0) ? g_Qp : (sel == 1) ? g_Kp : g_Vp;
#pragma unroll
    for (int mt = 0; mt < 4; mt++) {
#pragma unroll
        for (int nt = 0; nt < 8; nt++) {
            const int cg = n0 + wn64 + nt * 8 + 2 * t;
            const float b0 = bias[cg], b1 = bias[cg + 1];
#pragma unroll
            for (int half = 0; half < 2; half++) {
                const int rg_ = m0 + wm64 + mt * 16 + g + 8 * half;
                float v0 = acc[mt][nt][half * 2 + 0] + b0;
                float v1 = acc[mt][nt][half * 2 + 1] + b1;
                if (sel < 3) {
                    if (sel == 0) { v0 *= QSCALE; v1 *= QSCALE; }
                    const int s_ = rg_ >> 2, b_ = rg_ & 3;
                    const int h_ = cg >> 6,  dk = cg & 63;
                    uint2 o = make_uint2(f2tf32(v0), f2tf32(v1));
                    *(uint2*)&scat[(((size_t)(b_ * HH + h_)) * SS + s_) * DK + dk] = o;
                } else {
                    *(float2*)&out_ext[(size_t)rg_ * DDIM + cg] = make_float2(v0, v1);
                }
            }
        }
    }
}

__global__ void __launch_bounds__(128, 2) gemm_qkv2(
    const float* __restrict__ q, const float* __restrict__ k,
    const float* __restrict__ v,
    const float* __restrict__ wq, const float* __restrict__ wk,
    const float* __restrict__ wv,
    const float* __restrict__ bq, const float* __restrict__ bk,
    const float* __restrict__ bv)
{
    const int sel = blockIdx.z;
    const float* A = (sel == 0) ? q : (sel == 1) ? k : v;
    const float* W = (sel == 0) ? wq : (sel == 1) ? wk : wv;
    const float* bias = (sel == 0) ? bq : (sel == 1) ? bk : bv;
    gemm_body(A, W, bias, nullptr, sel);
}

__global__ void __launch_bounds__(128, 2) gemm_out(
    const float* __restrict__ wo, const float* __restrict__ bo,
    float* __restrict__ out)
{
    gemm_body(g_Xr, wo, bo, out, 3);
}

// ---------------------------------------------------------------------------
// Tensor-core causal flash attention — R11 shape (proven fastest).
// CTA: 256 q-rows, 8 warps x 32-row warp tiles. K/V: 64-key tiles, 2-slot
// smem double buffer, register-staged prefetch, ldmatrix frags.
// ONE barrier per tile iteration (double-buffer-safe, same argument as GEMM).
// ---------------------------------------------------------------------------
#define AR    68
#define ASTG  (64 * AR)
#define AT_SMEM ((2 * 256 * AR + 4 * ASTG) * 4)   // 208896 B

__global__ void __launch_bounds__(256, 1) attn_tc()
{
    extern __shared__ uint32_t dsm_a[];
    uint32_t* Qsm = dsm_a;
    uint32_t* Psm = Qsm + 256 * AR;
    uint32_t* Ksm = Psm + 256 * AR;
    uint32_t* Vsm = Ksm + 2 * ASTG;
    const uint32_t qsm_b = (uint32_t)__cvta_generic_to_shared(Qsm);
    const uint32_t psm_b = (uint32_t)__cvta_generic_to_shared(Psm);
    const uint32_t ksm_b = (uint32_t)__cvta_generic_to_shared(Ksm);

    const int bh   = blockIdx.x;
    const int qb   = (gridDim.y - 1) - blockIdx.y;   // heavy blocks first
    const int q0   = qb * 256;
    const int tid  = threadIdx.x;
    const int lane = tid & 31;
    const int warp = tid >> 5;
    const int g    = lane >> 2;
    const int t    = lane & 3;
    const int lr0  = warp * 32;

    const uint32_t a_ln = ((((lane >> 3) & 1) * 8 + (lane & 7)) * AR
                           + ((lane >> 4) << 2)) << 2;
    const uint32_t b_ln = (((((lane >> 4) << 3) + (lane & 7)) * AR)
                           + (((lane >> 3) & 1) << 2)) << 2;

    const uint32_t* Qg = g_Qp + (size_t)bh * SS * DK + (size_t)q0 * DK;
    const uint32_t* Kg = g_Kp + (size_t)bh * SS * DK;
    const uint32_t* Vg = g_Vp + (size_t)bh * SS * DK;

    const int ntiles = 4 * qb + 4;

    int lrow[4], lq[4];
#pragma unroll
    for (int i = 0; i < 4; i++) {
        const int c = tid + i * 256;
        lrow[i] = c >> 4;
        lq[i]   = (c & 15) * 4;
    }

    // Stage Q: 256 rows x 16 uint4 = 4096 chunks; 16 per thread
#pragma unroll
    for (int i = 0; i < 16; i++) {
        const int idx = tid + i * 256;
        const int row = idx >> 4;
        const int cq  = (idx & 15) * 4;
        *(uint4*)&Qsm[row * AR + cq] = *(const uint4*)(Qg + (size_t)row * DK + cq);
    }

    uint4 kst[4], vst[4];
#pragma unroll
    for (int i = 0; i < 4; i++) {
        kst[i] = *(const uint4*)(Kg + (size_t)lrow[i] * DK + lq[i]);
        vst[i] = *(const uint4*)(Vg + (size_t)lrow[i] * DK + lq[i]);
    }

    float m_[4], l_[4];
#pragma unroll
    for (int i = 0; i < 4; i++) { m_[i] = -1e30f; l_[i] = 0.f; }
    float oacc[2][8][4];
#pragma unroll
    for (int mt = 0; mt < 2; mt++)
#pragma unroll
        for (int nt = 0; nt < 8; nt++)
#pragma unroll
            for (int e = 0; e < 4; e++) oacc[mt][nt][e] = 0.f;

    for (int kt = 0; kt < ntiles; kt++) {
        const int s = kt & 1;
        const int kbase = kt * 64;

        // store staged K/V tile into slot s
#pragma unroll
        for (int i = 0; i < 4; i++) {
            *(uint4*)&Ksm[s * ASTG + lrow[i] * AR + lq[i]] = kst[i];
            *(uint4*)&Vsm[s * ASTG + lrow[i] * AR + lq[i]] = vst[i];
        }
        __syncthreads();

        // prefetch next tile into registers (overlaps compute)
        if (kt + 1 < ntiles) {
            const size_t base = (size_t)(kt + 1) * 64 * DK;
#pragma unroll
            for (int i = 0; i < 4; i++) {
                kst[i] = *(const uint4*)(Kg + base + (size_t)lrow[i] * DK + lq[i]);
                vst[i] = *(const uint4*)(Vg + base + (size_t)lrow[i] * DK + lq[i]);
            }
        }

        if (kbase <= q0 + lr0 + 31) {
            // ---- S = Q K^T (32 x 64) ----
            float sacc[2][8][4];
#pragma unroll
            for (int mt = 0; mt < 2; mt++)
#pragma unroll
                for (int nt = 0; nt < 8; nt++)
#pragma unroll
                    for (int e = 0; e < 4; e++) sacc[mt][nt][e] = 0.f;

            const uint32_t ksb = ksm_b + s * (ASTG * 4);
#pragma unroll
            for (int kk = 0; kk < 8; kk++) {
                uint32_t aq[2][4];
#pragma unroll
                for (int mt = 0; mt < 2; mt++)
                    ldsm_x4(aq[mt][0], aq[mt][1], aq[mt][2], aq[mt][3],
                            qsm_b + a_ln + (uint32_t)(((lr0 + mt * 16) * AR + kk * 8) * 4));
                uint32_t b[8][2];
#pragma unroll
                for (int p = 0; p < 4; p++)
                    ldsm_x4(b[2 * p][0], b[2 * p][1], b[2 * p + 1][0], b[2 * p + 1][1],
                            ksb + b_ln + (uint32_t)((p * 16 * AR + kk * 8) * 4));
#pragma unroll
                for (int nt = 0; nt < 8; nt++)
#pragma unroll
                    for (int mt = 0; mt < 2; mt++)
                        mma_tf32(sacc[mt][nt][0], sacc[mt][nt][1], sacc[mt][nt][2], sacc[mt][nt][3],
                                 aq[mt][0], aq[mt][1], aq[mt][2], aq[mt][3],
                                 b[nt][0], b[nt][1]);
            }

            // ---- causal mask (diagonal band only) ----
            if (kbase + 63 > q0 + lr0) {
#pragma unroll
                for (int mt = 0; mt < 2; mt++) {
                    const int rt_ = q0 + lr0 + mt * 16 + g;
                    const int rb_ = rt_ + 8;
#pragma unroll
                    for (int nt = 0; nt < 8; nt++) {
                        const int c0 = kbase + nt * 8 + 2 * t;
                        if (c0 > rt_)     sacc[mt][nt][0] = -1e30f;
                        if (c0 + 1 > rt_) sacc[mt][nt][1] = -1e30f;
                        if (c0 > rb_)     sacc[mt][nt][2] = -1e30f;
                        if (c0 + 1 > rb_) sacc[mt][nt][3] = -1e30f;
                    }
                }
            }

            // ---- online softmax ----
#pragma unroll
            for (int mt = 0; mt < 2; mt++) {
                float mxt = -1e30f, mxb = -1e30f;
#pragma unroll
                for (int nt = 0; nt < 8; nt++) {
                    mxt = fmaxf(mxt, fmaxf(sacc[mt][nt][0], sacc[mt][nt][1]));
                    mxb = fmaxf(mxb, fmaxf(sacc[mt][nt][2], sacc[mt][nt][3]));
                }
                mxt = fmaxf(mxt, __shfl_xor_sync(0xffffffffu, mxt, 1));
                mxt = fmaxf(mxt, __shfl_xor_sync(0xffffffffu, mxt, 2));
                mxb = fmaxf(mxb, __shfl_xor_sync(0xffffffffu, mxb, 1));
                mxb = fmaxf(mxb, __shfl_xor_sync(0xffffffffu, mxb, 2));

                const int rc0 = mt * 2, rc1 = mt * 2 + 1;
                const float mnt = fmaxf(m_[rc0], mxt);
                const float mnb = fmaxf(m_[rc1], mxb);
                const float ct = ex2((m_[rc0] - mnt) * LOG2E);
                const float cb = ex2((m_[rc1] - mnb) * LOG2E);
                m_[rc0] = mnt; m_[rc1] = mnb;

                float st_ = 0.f, sb_ = 0.f;
                uint32_t* pr0 = Psm + (lr0 + mt * 16 + g) * AR;
                uint32_t* pr1 = pr0 + 8 * AR;
#pragma unroll
                for (int nt = 0; nt < 8; nt++) {
                    const float p0 = ex2((sacc[mt][nt][0] - mnt) * LOG2E);
                    const float p1 = ex2((sacc[mt][nt][1] - mnt) * LOG2E);
                    const float p2 = ex2((sacc[mt][nt][2] - mnb) * LOG2E);
                    const float p3 = ex2((sacc[mt][nt][3] - mnb) * LOG2E);
                    st_ += p0 + p1; sb_ += p2 + p3;
                    pr0[nt * 8 + 2 * t]     = f2tf32(p0);
                    pr0[nt * 8 + 2 * t + 1] = f2tf32(p1);
                    pr1[nt * 8 + 2 * t]     = f2tf32(p2);
                    pr1[nt * 8 + 2 * t + 1] = f2tf32(p3);
                }
                st_ += __shfl_xor_sync(0xffffffffu, st_, 1);
                st_ += __shfl_xor_sync(0xffffffffu, st_, 2);
                sb_ += __shfl_xor_sync(0xffffffffu, sb_, 1);
                sb_ += __shfl_xor_sync(0xffffffffu, sb_, 2);
                l_[rc0] = l_[rc0] * ct + st_;
                l_[rc1] = l_[rc1] * cb + sb_;
#pragma unroll
                for (int nt = 0; nt < 8; nt++) {
                    oacc[mt][nt][0] *= ct; oacc[mt][nt][1] *= ct;
                    oacc[mt][nt][2] *= cb; oacc[mt][nt][3] *= cb;
                }
            }
            __syncwarp();

            // ---- O += P V (32 x 64 x 64) ----
            const uint32_t* Vs_ = Vsm + s * ASTG;
#pragma unroll
            for (int kk = 0; kk < 8; kk++) {
                uint32_t ap[2][4];
#pragma unroll
                for (int mt = 0; mt < 2; mt++)
                    ldsm_x4(ap[mt][0], ap[mt][1], ap[mt][2], ap[mt][3],
                            psm_b + a_ln + (uint32_t)(((lr0 + mt * 16) * AR + kk * 8) * 4));
                const uint32_t* vp0 = Vs_ + (kk * 8 + t) * AR;
                const uint32_t* vp1 = Vs_ + (kk * 8 + t + 4) * AR;
#pragma unroll
                for (int nt = 0; nt < 8; nt++) {
                    const uint32_t b0 = vp0[nt * 8 + g];
                    const uint32_t b1 = vp1[nt * 8 + g];
#pragma unroll
                    for (int mt = 0; mt < 2; mt++)
                        mma_tf32(oacc[mt][nt][0], oacc[mt][nt][1], oacc[mt][nt][2], oacc[mt][nt][3],
                                 ap[mt][0], ap[mt][1], ap[mt][2], ap[mt][3], b0, b1);
                }
            }
        }
    }

    // ---- epilogue ----
    const int b_ = bh >> 4;
    const int h_ = bh & 15;
#pragma unroll
    for (int mt = 0; mt < 2; mt++) {
#pragma unroll
        for (int half = 0; half < 2; half++) {
            const int rc = mt * 2 + half;
            const float inv = 1.0f / l_[rc];
            const int row = q0 + lr0 + mt * 16 + g + 8 * half;
            float* dst = g_Xr + ((size_t)row * BBATCH + b_) * DDIM + h_ * DK;
#pragma unroll
            for (int nt = 0; nt < 8; nt++) {
                const int c = nt * 8 + 2 * t;
                *(float2*)(dst + c) = make_float2(oacc[mt][nt][half * 2 + 0] * inv,
                                                  oacc[mt][nt][half * 2 + 1] * inv);
            }
        }
    }
}

// ---------------------------------------------------------------------------
// Launch: gemm_qkv2(0), attn(1), gemm_out(2)
// ---------------------------------------------------------------------------
extern "C" void kernel_launch(void* const* d_in, const int* in_sizes, int n_in,
                              void* d_out, int out_size)
{
    (void)in_sizes; (void)n_in; (void)out_size;
    const float* query = (const float*)d_in[0];
    const float* key   = (const float*)d_in[1];
    const float* value = (const float*)d_in[2];
    const float* Wq = (const float*)d_in[4];
    const float* bq = (const float*)d_in[5];
    const float* Wk = (const float*)d_in[6];
    const float* bk = (const float*)d_in[7];
    const float* Wv = (const float*)d_in[8];
    const float* bv = (const float*)d_in[9];
    const float* Wo = (const float*)d_in[10];
    const float* bo = (const float*)d_in[11];
    float* out = (float*)d_out;

    cudaFuncSetAttribute(attn_tc, cudaFuncAttributeMaxDynamicSharedMemorySize, AT_SMEM);

    gemm_qkv2<<<dim3(DDIM / 128, MM / 128, 3), 128>>>(
        query, key, value, Wq, Wk, Wv, bq, bk, bv);

    attn_tc<<<dim3(BBATCH * HH, SS / 256), 256, AT_SMEM>>>();

    gemm_out<<<dim3(DDIM / 128, MM / 128), 128>>>(Wo, bo, out);
}